// round 5
// baseline (speedup 1.0000x reference)
#include <cuda_runtime.h>
#include <cuda_bf16.h>
#include <stdint.h>
#include <math.h>

#define M_TOK 16384
#define N_EMB 16384
#define KDIM  256
#define HWSZ  1024
#define NZ    (M_TOK * KDIM)
#define FIXLEN 30.0f

// ---------------- device scratch (static, no allocation) ----------------
__device__ float          g_zflat[M_TOK * KDIM];
__device__ __nv_bfloat16  g_z_hi[M_TOK * KDIM];
__device__ __nv_bfloat16  g_z_lo[M_TOK * KDIM];
__device__ __nv_bfloat16  g_e_hi[N_EMB * KDIM];
__device__ __nv_bfloat16  g_e_lo[N_EMB * KDIM];
__device__ float          g_enorm2[N_EMB];
__device__ int            g_bestidx[M_TOK];
__device__ float          g_normpart[64];
__device__ float          g_scalars[2];
__device__ float          g_diffpart[256];

// ---------------- small helpers ----------------
__device__ __forceinline__ uint32_t smem_u32(const void* p) {
    uint32_t a;
    asm("{ .reg .u64 t; cvta.to.shared.u64 t, %1; cvt.u32.u64 %0, t; }" : "=r"(a) : "l"(p));
    return a;
}
__device__ __forceinline__ void cp_async16(uint32_t dst, const void* src) {
    uint64_t g = __cvta_generic_to_global(src);
    asm volatile("cp.async.cg.shared.global [%0], [%1], 16;" :: "r"(dst), "l"(g));
}
__device__ __forceinline__ void cp_commit() { asm volatile("cp.async.commit_group;"); }
template <int N> __device__ __forceinline__ void cp_wait() {
    asm volatile("cp.async.wait_group %0;" :: "n"(N));
}
__device__ __forceinline__ void ldsm4(uint32_t* r, uint32_t addr) {
    asm volatile("ldmatrix.sync.aligned.m8n8.x4.shared.b16 {%0,%1,%2,%3}, [%4];"
                 : "=r"(r[0]), "=r"(r[1]), "=r"(r[2]), "=r"(r[3]) : "r"(addr));
}
__device__ __forceinline__ void mma16816(float* c, const uint32_t* a, uint32_t b0, uint32_t b1) {
    asm volatile("mma.sync.aligned.m16n8k16.row.col.f32.bf16.bf16.f32 "
                 "{%0,%1,%2,%3}, {%4,%5,%6,%7}, {%8,%9}, {%0,%1,%2,%3};"
                 : "+f"(c[0]), "+f"(c[1]), "+f"(c[2]), "+f"(c[3])
                 : "r"(a[0]), "r"(a[1]), "r"(a[2]), "r"(a[3]), "r"(b0), "r"(b1));
}

__device__ __forceinline__ void split4(float4 v, uint2& ph, uint2& pl) {
    __nv_bfloat16 h0 = __float2bfloat16(v.x), h1 = __float2bfloat16(v.y),
                  h2 = __float2bfloat16(v.z), h3 = __float2bfloat16(v.w);
    __nv_bfloat16 l0 = __float2bfloat16(v.x - __bfloat162float(h0));
    __nv_bfloat16 l1 = __float2bfloat16(v.y - __bfloat162float(h1));
    __nv_bfloat16 l2 = __float2bfloat16(v.z - __bfloat162float(h2));
    __nv_bfloat16 l3 = __float2bfloat16(v.w - __bfloat162float(h3));
    ph.x = (uint32_t)__bfloat16_as_ushort(h0) | ((uint32_t)__bfloat16_as_ushort(h1) << 16);
    ph.y = (uint32_t)__bfloat16_as_ushort(h2) | ((uint32_t)__bfloat16_as_ushort(h3) << 16);
    pl.x = (uint32_t)__bfloat16_as_ushort(l0) | ((uint32_t)__bfloat16_as_ushort(l1) << 16);
    pl.y = (uint32_t)__bfloat16_as_ushort(l2) | ((uint32_t)__bfloat16_as_ushort(l3) << 16);
}

// ---------------- kernel 1: transpose z, token norms, bf16 split ----------------
__global__ void k_prep(const float* __restrict__ z) {
    int t  = blockIdx.x * 256 + threadIdx.x;
    int b  = t >> 10;
    int hw = t & 1023;
    const float* zp = z + (size_t)b * (KDIM * HWSZ) + hw;
    float acc = 0.0f;
#pragma unroll 4
    for (int c = 0; c < KDIM; c += 4) {
        float v0 = zp[(c + 0) * HWSZ];
        float v1 = zp[(c + 1) * HWSZ];
        float v2 = zp[(c + 2) * HWSZ];
        float v3 = zp[(c + 3) * HWSZ];
        acc += v0 * v0 + v1 * v1 + v2 * v2 + v3 * v3;
        float4 w = make_float4(v0, v1, v2, v3);
        *(float4*)&g_zflat[t * KDIM + c] = w;
        uint2 ph, pl; split4(w, ph, pl);
        *(uint2*)&g_z_hi[t * KDIM + c] = ph;
        *(uint2*)&g_z_lo[t * KDIM + c] = pl;
    }
    float nrm = sqrtf(acc);
    __shared__ float sred[256];
    sred[threadIdx.x] = nrm;
    __syncthreads();
    for (int s = 128; s > 0; s >>= 1) {
        if (threadIdx.x < s) sred[threadIdx.x] += sred[threadIdx.x + s];
        __syncthreads();
    }
    if (threadIdx.x == 0) g_normpart[blockIdx.x] = sred[0];
}

// ---------------- kernel 2 ----------------
__global__ void k_scale() {
    __shared__ float s[64];
    s[threadIdx.x] = g_normpart[threadIdx.x];
    __syncthreads();
    for (int st = 32; st > 0; st >>= 1) {
        if (threadIdx.x < st) s[threadIdx.x] += s[threadIdx.x + st];
        __syncthreads();
    }
    if (threadIdx.x == 0) {
        float pre_len = s[0] / (float)M_TOK;
        float scale = (pre_len >= FIXLEN) ? (FIXLEN / pre_len) : 1.0f;
        g_scalars[0] = scale;
        g_scalars[1] = 2.0f * scale / FIXLEN;
    }
}

// ---------------- kernel 3 ----------------
__global__ void k_enorm(const float* __restrict__ emb) {
    int w    = threadIdx.x >> 5;
    int lane = threadIdx.x & 31;
    int r    = blockIdx.x * 8 + w;
    const float4* ep = (const float4*)(emb + (size_t)r * KDIM);
    float4 a = ep[lane];
    float4 b = ep[lane + 32];
    float acc = a.x * a.x + a.y * a.y + a.z * a.z + a.w * a.w
              + b.x * b.x + b.y * b.y + b.z * b.z + b.w * b.w;
    uint2 ph, pl;
    split4(a, ph, pl);
    *(uint2*)&g_e_hi[(size_t)r * KDIM + 4 * lane] = ph;
    *(uint2*)&g_e_lo[(size_t)r * KDIM + 4 * lane] = pl;
    split4(b, ph, pl);
    *(uint2*)&g_e_hi[(size_t)r * KDIM + 128 + 4 * lane] = ph;
    *(uint2*)&g_e_lo[(size_t)r * KDIM + 128 + 4 * lane] = pl;
#pragma unroll
    for (int s = 16; s > 0; s >>= 1)
        acc += __shfl_down_sync(0xffffffffu, acc, s);
    if (lane == 0) g_enorm2[r] = acc;
}

// ---------------- kernel 4: HMMA bf16x3 GEMM + fused argmin ----------------
// 512 threads, warp grid 4(m) x 4(n), warp tile 32x32. A resident in SMEM.
// B stream = 1024 chunks (128 n-tiles x 8 chunks of 128n x 64k):
//   chunks 0-3 = e_hi k0..k192 (each fused-dual pass: a_hi AND a_lo, B frags reused),
//   chunks 4-7 = e_lo k0..k192 (single pass vs a_hi).
// 4 SMEM buffers, prefetch distance 3, ONE syncthreads per chunk, zero drains.
// Epilogue reads g_enorm2 via __ldg (L1-resident), register-only.
#define SM_A_BYTES 131072
#define SM_B_BYTES 16384

__device__ __forceinline__ uint32_t a_sw(int row, int col) {   // col in [0,512)
    return (uint32_t)(row * 1024 + ((col >> 6) << 7)
           + (((((col >> 3) & 7) ^ (row & 7))) << 4) + ((col & 7) << 1));
}
__device__ __forceinline__ uint32_t b_sw64(int row, int col) { // col in [0,64)
    return (uint32_t)(row * 128 + ((((col >> 3) ^ (row & 7))) << 4) + ((col & 7) << 1));
}

extern __shared__ char dsm[];

__device__ __forceinline__ void issue_chunk(int c, int tid, uint32_t Bbuf0) {
    const int iter = c >> 3, sub = c & 7;
    const __nv_bfloat16* src = (sub < 4) ? g_e_hi : g_e_lo;
    const int kbase = (sub & 3) * 64;
    const uint32_t dst = Bbuf0 + (uint32_t)(c & 3) * SM_B_BYTES;
    const size_t rb = (size_t)(iter * 128) * KDIM + kbase;
#pragma unroll
    for (int f = tid; f < 1024; f += 512) {
        int row = f >> 3, k = (f & 7) * 8;
        cp_async16(dst + b_sw64(row, k), src + rb + (size_t)row * KDIM + k);
    }
    cp_commit();
}

// dual pass: B chunk (e_hi) vs BOTH a_hi (cols kbase..) and a_lo (cols 256+kbase..)
__device__ __forceinline__ void pass_dual(
    uint32_t As, uint32_t Bb, int kbase,
    int arow_base, int akof, int brow_base, int bkof, float acc[2][4][4])
{
    uint32_t ah[2][2][4], al[2][2][4], br[2][2][4];
#pragma unroll
    for (int mt = 0; mt < 2; mt++) {
        ldsm4(ah[0][mt], As + a_sw(arow_base + mt * 16, kbase + akof));
        ldsm4(al[0][mt], As + a_sw(arow_base + mt * 16, 256 + kbase + akof));
    }
#pragma unroll
    for (int np = 0; np < 2; np++)
        ldsm4(br[0][np], Bb + b_sw64(brow_base + np * 16, bkof));
#pragma unroll
    for (int kk = 0; kk < 4; kk++) {
        const int cur = kk & 1, nxt = cur ^ 1;
        if (kk < 3) {
            const int ac = kbase + (kk + 1) * 16 + akof;
            const int bc = (kk + 1) * 16 + bkof;
#pragma unroll
            for (int mt = 0; mt < 2; mt++) {
                ldsm4(ah[nxt][mt], As + a_sw(arow_base + mt * 16, ac));
                ldsm4(al[nxt][mt], As + a_sw(arow_base + mt * 16, 256 + ac));
            }
#pragma unroll
            for (int np = 0; np < 2; np++)
                ldsm4(br[nxt][np], Bb + b_sw64(brow_base + np * 16, bc));
        }
#pragma unroll
        for (int mt = 0; mt < 2; mt++)
#pragma unroll
            for (int nt = 0; nt < 4; nt++)
                mma16816(acc[mt][nt], ah[cur][mt],
                         br[cur][nt >> 1][(nt & 1) * 2], br[cur][nt >> 1][(nt & 1) * 2 + 1]);
#pragma unroll
        for (int mt = 0; mt < 2; mt++)
#pragma unroll
            for (int nt = 0; nt < 4; nt++)
                mma16816(acc[mt][nt], al[cur][mt],
                         br[cur][nt >> 1][(nt & 1) * 2], br[cur][nt >> 1][(nt & 1) * 2 + 1]);
    }
}

// single pass: B chunk (e_lo) vs a_hi (cols kbase..)
__device__ __forceinline__ void pass_single(
    uint32_t As, uint32_t Bb, int kbase,
    int arow_base, int akof, int brow_base, int bkof, float acc[2][4][4])
{
    uint32_t ah[2][2][4], br[2][2][4];
#pragma unroll
    for (int mt = 0; mt < 2; mt++)
        ldsm4(ah[0][mt], As + a_sw(arow_base + mt * 16, kbase + akof));
#pragma unroll
    for (int np = 0; np < 2; np++)
        ldsm4(br[0][np], Bb + b_sw64(brow_base + np * 16, bkof));
#pragma unroll
    for (int kk = 0; kk < 4; kk++) {
        const int cur = kk & 1, nxt = cur ^ 1;
        if (kk < 3) {
            const int ac = kbase + (kk + 1) * 16 + akof;
            const int bc = (kk + 1) * 16 + bkof;
#pragma unroll
            for (int mt = 0; mt < 2; mt++)
                ldsm4(ah[nxt][mt], As + a_sw(arow_base + mt * 16, ac));
#pragma unroll
            for (int np = 0; np < 2; np++)
                ldsm4(br[nxt][np], Bb + b_sw64(brow_base + np * 16, bc));
        }
#pragma unroll
        for (int mt = 0; mt < 2; mt++)
#pragma unroll
            for (int nt = 0; nt < 4; nt++)
                mma16816(acc[mt][nt], ah[cur][mt],
                         br[cur][nt >> 1][(nt & 1) * 2], br[cur][nt >> 1][(nt & 1) * 2 + 1]);
    }
}

__global__ void __launch_bounds__(512, 1) k_gemm_h() {
    const int tid  = threadIdx.x;
    const int lane = tid & 31;
    const int wid  = tid >> 5;
    const int wm   = wid & 3;
    const int wn   = wid >> 2;
    const int m0   = blockIdx.x * 128;
    const int g    = lane >> 2;
    const int cc   = lane & 3;
    const int sub  = lane >> 3;
    const int r8   = lane & 7;

    uint32_t raw  = smem_u32(dsm);
    uint32_t base = (raw + 255u) & ~255u;
    char*    basep = dsm + (base - raw);
    const uint32_t As = base;
    const uint32_t Bbuf0 = base + SM_A_BYTES;

    // ---- load A (hi|lo) once ----
#pragma unroll
    for (int seg = 0; seg < 2; seg++) {
        const __nv_bfloat16* src = seg ? g_z_lo : g_z_hi;
        for (int f = tid; f < 4096; f += 512) {
            int row = f >> 5;
            int k   = (f & 31) * 8;
            cp_async16(As + a_sw(row, seg * 256 + k),
                       src + (size_t)(m0 + row) * KDIM + k);
        }
    }
    cp_commit();
    cp_wait<0>();
    __syncthreads();

    const float alpha = g_scalars[1];

    float bestv[4];
    int   besti[4];
#pragma unroll
    for (int i = 0; i < 4; i++) { bestv[i] = 3.4e38f; besti[i] = 0; }

    const int arow_base = wm * 32 + ((sub & 1) << 3) + r8;
    const int akof      = (sub >> 1) << 3;
    const int brow_base = wn * 32 + ((sub >> 1) << 3) + r8;
    const int bkof      = (sub & 1) << 3;

    // prologue: 3 chunks in flight
    issue_chunk(0, tid, Bbuf0);
    issue_chunk(1, tid, Bbuf0);
    issue_chunk(2, tid, Bbuf0);

    float acc[2][4][4];
#pragma unroll
    for (int a = 0; a < 2; a++)
#pragma unroll
        for (int b = 0; b < 4; b++)
#pragma unroll
            for (int d = 0; d < 4; d++) acc[a][b][d] = 0.0f;

    const float2* e2 = (const float2*)g_enorm2;

#pragma unroll 1
    for (int c = 0; c < 1024; c++) {
        if (c < 1022)      cp_wait<2>();
        else if (c == 1022) cp_wait<1>();
        else               cp_wait<0>();
        __syncthreads();
        if (c < 1021) issue_chunk(c + 3, tid, Bbuf0);

        const int sub8 = c & 7;
        const int kbase = (sub8 & 3) * 64;
        const uint32_t Bb = Bbuf0 + (uint32_t)(c & 3) * SM_B_BYTES;
        if (sub8 < 4)
            pass_dual(As, Bb, kbase, arow_base, akof, brow_base, bkof, acc);
        else
            pass_single(As, Bb, kbase, arow_base, akof, brow_base, bkof, acc);

        if (sub8 == 7) {
            const int n0 = (c >> 3) * 128;
            // register-only argmin epilogue (overlaps in-flight cp.async)
#pragma unroll
            for (int mt = 0; mt < 2; mt++) {
#pragma unroll
                for (int nt = 0; nt < 4; nt++) {
                    const int nloc = wn * 32 + nt * 8 + 2 * cc;
                    const int gn = n0 + nloc;
                    float2 ev = __ldg(e2 + ((unsigned)gn >> 1));
                    float v0 = fmaf(-alpha, acc[mt][nt][0], ev.x);
                    float v1 = fmaf(-alpha, acc[mt][nt][1], ev.y);
                    float v2 = fmaf(-alpha, acc[mt][nt][2], ev.x);
                    float v3 = fmaf(-alpha, acc[mt][nt][3], ev.y);
                    const int i0 = mt * 2, i1 = mt * 2 + 1;
                    if (v0 < bestv[i0]) { bestv[i0] = v0; besti[i0] = gn; }
                    if (v1 < bestv[i0]) { bestv[i0] = v1; besti[i0] = gn + 1; }
                    if (v2 < bestv[i1]) { bestv[i1] = v2; besti[i1] = gn; }
                    if (v3 < bestv[i1]) { bestv[i1] = v3; besti[i1] = gn + 1; }
                    acc[mt][nt][0] = 0.0f; acc[mt][nt][1] = 0.0f;
                    acc[mt][nt][2] = 0.0f; acc[mt][nt][3] = 0.0f;
                }
            }
        }
    }

    // ---- final per-row reduction (16 candidates per row) ----
    __syncthreads();
    float* Rv = (float*)basep;
    int*   Ri = (int*)(basep + 128 * 16 * sizeof(float));
    const int slot = wn * 4 + cc;
#pragma unroll
    for (int mt = 0; mt < 2; mt++) {
#pragma unroll
        for (int h = 0; h < 2; h++) {
            int mloc = wm * 32 + mt * 16 + h * 8 + g;
            Rv[mloc * 16 + slot] = bestv[mt * 2 + h];
            Ri[mloc * 16 + slot] = besti[mt * 2 + h];
        }
    }
    __syncthreads();
    if (tid < 128) {
        float bv = Rv[tid * 16];
        int   bi = Ri[tid * 16];
#pragma unroll
        for (int t = 1; t < 16; t++) {
            float v = Rv[tid * 16 + t];
            int  ix = Ri[tid * 16 + t];
            if (v < bv || (v == bv && ix < bi)) { bv = v; bi = ix; }
        }
        g_bestidx[m0 + tid] = bi;
    }
}

// ---------------- kernel 5 ----------------
__global__ void k_gather(const float* __restrict__ emb, float* __restrict__ out) {
    float scale = g_scalars[0];
    float lsum = 0.0f;
    for (int e = blockIdx.x * 256 + threadIdx.x; e < M_TOK * KDIM; e += 256 * 256) {
        int t = e >> 8;
        int c = e & 255;
        int idx = g_bestidx[t];
        float zq = emb[(size_t)idx * KDIM + c] * FIXLEN;
        float zt = g_zflat[e] * scale;
        float d = zq - zt;
        lsum += d * d;
        int b  = t >> 10;
        int hw = t & 1023;
        out[(size_t)b * (KDIM * HWSZ) + (size_t)c * HWSZ + hw] = zq;
    }
    __shared__ float sred[256];
    sred[threadIdx.x] = lsum;
    __syncthreads();
    for (int s = 128; s > 0; s >>= 1) {
        if (threadIdx.x < s) sred[threadIdx.x] += sred[threadIdx.x + s];
        __syncthreads();
    }
    if (threadIdx.x == 0) g_diffpart[blockIdx.x] = sred[0];
}

// ---------------- kernel 6 ----------------
__global__ void k_final(float* __restrict__ out, int out_size) {
    __shared__ float s[256];
    s[threadIdx.x] = g_diffpart[threadIdx.x];
    __syncthreads();
    for (int st = 128; st > 0; st >>= 1) {
        if (threadIdx.x < st) s[threadIdx.x] += s[threadIdx.x + st];
        __syncthreads();
    }
    float diff = 0.25f * s[0] / (float)(M_TOK * KDIM);
    if (threadIdx.x == 0 && out_size > NZ) out[NZ] = diff;
    if (out_size >= NZ + 1 + M_TOK) {
        for (int t = threadIdx.x; t < M_TOK; t += 256)
            out[NZ + 1 + t] = (float)g_bestidx[t];
    }
}

// ---------------- launch ----------------
extern "C" void kernel_launch(void* const* d_in, const int* in_sizes, int n_in,
                              void* d_out, int out_size) {
    const float* z   = (const float*)d_in[0];
    const float* emb = (const float*)d_in[1];
    float* out = (float*)d_out;
    (void)in_sizes; (void)n_in;

    const int gemm_smem = 256 + SM_A_BYTES + 4 * SM_B_BYTES;  // 196,864 B
    cudaFuncSetAttribute(k_gemm_h, cudaFuncAttributeMaxDynamicSharedMemorySize, gemm_smem);

    k_prep<<<M_TOK / 256, 256>>>(z);
    k_scale<<<1, 64>>>();
    k_enorm<<<N_EMB / 8, 256>>>(emb);
    k_gemm_h<<<M_TOK / 128, 512, gemm_smem>>>();
    k_gather<<<256, 256>>>(emb, out);
    k_final<<<1, 256>>>(out, out_size);
}

// round 6
// speedup vs baseline: 1.2513x; 1.2513x over previous
#include <cuda_runtime.h>
#include <cuda_bf16.h>
#include <stdint.h>
#include <math.h>

#define M_TOK 16384
#define N_EMB 16384
#define KDIM  256
#define HWSZ  1024
#define NZ    (M_TOK * KDIM)
#define FIXLEN 30.0f

#define NUM_CTAS   152
#define RUNS_TOTAL 2048   /* 128 m-tiles x 16 runs; run = 8 n-subtiles of 128 */

// ---------------- device scratch (static, no allocation) ----------------
__device__ float          g_zflat[M_TOK * KDIM];
__device__ __nv_bfloat16  g_z_hi[M_TOK * KDIM];
__device__ __nv_bfloat16  g_z_lo[M_TOK * KDIM];
__device__ __nv_bfloat16  g_e_hi[N_EMB * KDIM];
__device__ __nv_bfloat16  g_e_lo[N_EMB * KDIM];
__device__ float          g_enorm2[N_EMB];
__device__ unsigned long long g_best[M_TOK];   // packed (ordered-float << 32) | idx
__device__ unsigned       g_unit_ctr;
__device__ float          g_normpart[64];
__device__ float          g_scalars[2];
__device__ float          g_diffpart[256];

// ---------------- small helpers ----------------
__device__ __forceinline__ uint32_t smem_u32(const void* p) {
    uint32_t a;
    asm("{ .reg .u64 t; cvta.to.shared.u64 t, %1; cvt.u32.u64 %0, t; }" : "=r"(a) : "l"(p));
    return a;
}
__device__ __forceinline__ void cp_async16(uint32_t dst, const void* src) {
    uint64_t g = __cvta_generic_to_global(src);
    asm volatile("cp.async.cg.shared.global [%0], [%1], 16;" :: "r"(dst), "l"(g));
}
__device__ __forceinline__ void cp_commit() { asm volatile("cp.async.commit_group;"); }
template <int N> __device__ __forceinline__ void cp_wait() {
    asm volatile("cp.async.wait_group %0;" :: "n"(N));
}
__device__ __forceinline__ void ldsm4(uint32_t* r, uint32_t addr) {
    asm volatile("ldmatrix.sync.aligned.m8n8.x4.shared.b16 {%0,%1,%2,%3}, [%4];"
                 : "=r"(r[0]), "=r"(r[1]), "=r"(r[2]), "=r"(r[3]) : "r"(addr));
}
__device__ __forceinline__ void mma16816(float* c, const uint32_t* a, uint32_t b0, uint32_t b1) {
    asm volatile("mma.sync.aligned.m16n8k16.row.col.f32.bf16.bf16.f32 "
                 "{%0,%1,%2,%3}, {%4,%5,%6,%7}, {%8,%9}, {%0,%1,%2,%3};"
                 : "+f"(c[0]), "+f"(c[1]), "+f"(c[2]), "+f"(c[3])
                 : "r"(a[0]), "r"(a[1]), "r"(a[2]), "r"(a[3]), "r"(b0), "r"(b1));
}
__device__ __forceinline__ unsigned long long pack_key(float v, unsigned idx) {
    unsigned u = __float_as_uint(v);
    u = (u & 0x80000000u) ? ~u : (u | 0x80000000u);
    return ((unsigned long long)u << 32) | idx;
}

__device__ __forceinline__ void split4(float4 v, uint2& ph, uint2& pl) {
    __nv_bfloat16 h0 = __float2bfloat16(v.x), h1 = __float2bfloat16(v.y),
                  h2 = __float2bfloat16(v.z), h3 = __float2bfloat16(v.w);
    __nv_bfloat16 l0 = __float2bfloat16(v.x - __bfloat162float(h0));
    __nv_bfloat16 l1 = __float2bfloat16(v.y - __bfloat162float(h1));
    __nv_bfloat16 l2 = __float2bfloat16(v.z - __bfloat162float(h2));
    __nv_bfloat16 l3 = __float2bfloat16(v.w - __bfloat162float(h3));
    ph.x = (uint32_t)__bfloat16_as_ushort(h0) | ((uint32_t)__bfloat16_as_ushort(h1) << 16);
    ph.y = (uint32_t)__bfloat16_as_ushort(h2) | ((uint32_t)__bfloat16_as_ushort(h3) << 16);
    pl.x = (uint32_t)__bfloat16_as_ushort(l0) | ((uint32_t)__bfloat16_as_ushort(l1) << 16);
    pl.y = (uint32_t)__bfloat16_as_ushort(l2) | ((uint32_t)__bfloat16_as_ushort(l3) << 16);
}

// ---------------- kernel 1: transpose z, token norms, bf16 split ----------------
__global__ void k_prep(const float* __restrict__ z) {
    int t  = blockIdx.x * 256 + threadIdx.x;
    int b  = t >> 10;
    int hw = t & 1023;
    const float* zp = z + (size_t)b * (KDIM * HWSZ) + hw;
    float acc = 0.0f;
    g_best[t] = 0xFFFFFFFFFFFFFFFFull;
#pragma unroll 4
    for (int c = 0; c < KDIM; c += 4) {
        float v0 = zp[(c + 0) * HWSZ];
        float v1 = zp[(c + 1) * HWSZ];
        float v2 = zp[(c + 2) * HWSZ];
        float v3 = zp[(c + 3) * HWSZ];
        acc += v0 * v0 + v1 * v1 + v2 * v2 + v3 * v3;
        float4 w = make_float4(v0, v1, v2, v3);
        *(float4*)&g_zflat[t * KDIM + c] = w;
        uint2 ph, pl; split4(w, ph, pl);
        *(uint2*)&g_z_hi[t * KDIM + c] = ph;
        *(uint2*)&g_z_lo[t * KDIM + c] = pl;
    }
    float nrm = sqrtf(acc);
    __shared__ float sred[256];
    sred[threadIdx.x] = nrm;
    __syncthreads();
    for (int s = 128; s > 0; s >>= 1) {
        if (threadIdx.x < s) sred[threadIdx.x] += sred[threadIdx.x + s];
        __syncthreads();
    }
    if (threadIdx.x == 0) g_normpart[blockIdx.x] = sred[0];
}

// ---------------- kernel 2: scale + counter reset ----------------
__global__ void k_scale() {
    __shared__ float s[64];
    s[threadIdx.x] = g_normpart[threadIdx.x];
    __syncthreads();
    for (int st = 32; st > 0; st >>= 1) {
        if (threadIdx.x < st) s[threadIdx.x] += s[threadIdx.x + st];
        __syncthreads();
    }
    if (threadIdx.x == 0) {
        float pre_len = s[0] / (float)M_TOK;
        float scale = (pre_len >= FIXLEN) ? (FIXLEN / pre_len) : 1.0f;
        g_scalars[0] = scale;
        g_scalars[1] = 2.0f * scale / FIXLEN;
        g_unit_ctr = 0u;
    }
}

// ---------------- kernel 3 ----------------
__global__ void k_enorm(const float* __restrict__ emb) {
    int w    = threadIdx.x >> 5;
    int lane = threadIdx.x & 31;
    int r    = blockIdx.x * 8 + w;
    const float4* ep = (const float4*)(emb + (size_t)r * KDIM);
    float4 a = ep[lane];
    float4 b = ep[lane + 32];
    float acc = a.x * a.x + a.y * a.y + a.z * a.z + a.w * a.w
              + b.x * b.x + b.y * b.y + b.z * b.z + b.w * b.w;
    uint2 ph, pl;
    split4(a, ph, pl);
    *(uint2*)&g_e_hi[(size_t)r * KDIM + 4 * lane] = ph;
    *(uint2*)&g_e_lo[(size_t)r * KDIM + 4 * lane] = pl;
    split4(b, ph, pl);
    *(uint2*)&g_e_hi[(size_t)r * KDIM + 128 + 4 * lane] = ph;
    *(uint2*)&g_e_lo[(size_t)r * KDIM + 128 + 4 * lane] = pl;
#pragma unroll
    for (int s = 16; s > 0; s >>= 1)
        acc += __shfl_down_sync(0xffffffffu, acc, s);
    if (lane == 0) g_enorm2[r] = acc;
}

// ---------------- kernel 4: persistent HMMA bf16x3 GEMM + fused argmin ----------------
#define SM_A_BYTES 131072
#define SM_B_BYTES 32768

__device__ __forceinline__ uint32_t a_sw(int row, int col) {   // col in [0,512)
    return (uint32_t)(row * 1024 + ((col >> 6) << 7)
           + (((((col >> 3) & 7) ^ (row & 7))) << 4) + ((col & 7) << 1));
}
__device__ __forceinline__ uint32_t b_sw(int row, int col) {   // col in [0,128)
    return (uint32_t)(row * 256 + ((col >> 6) << 7)
           + (((((col >> 3) & 7) ^ (row & 7))) << 4) + ((col & 7) << 1));
}

extern __shared__ char dsm[];

// issue one 128n x 128k B chunk (32KB) into buffer
__device__ __forceinline__ void issue_b(const __nv_bfloat16* src, int n0, int kbase,
                                        uint32_t dst, int tid) {
#pragma unroll
    for (int f = tid; f < 2048; f += 512) {
        int row = f >> 4, k = (f & 15) * 8;
        cp_async16(dst + b_sw(row, k), src + (size_t)(n0 + row) * KDIM + kbase + k);
    }
    cp_commit();
}

// fused dual: B chunk (e_hi) vs a_hi (cols abase..) AND a_lo (cols 256+abase..)
__device__ __forceinline__ void pass_dual(
    uint32_t As, uint32_t Bb, int abase,
    int arow_base, int akof, int brow_base, int bkof, float acc[2][4][4])
{
    uint32_t ah[2][2][4], al[2][2][4], br[2][2][4];
#pragma unroll
    for (int mt = 0; mt < 2; mt++) {
        ldsm4(ah[0][mt], As + a_sw(arow_base + mt * 16, abase + akof));
        ldsm4(al[0][mt], As + a_sw(arow_base + mt * 16, 256 + abase + akof));
    }
#pragma unroll
    for (int np = 0; np < 2; np++)
        ldsm4(br[0][np], Bb + b_sw(brow_base + np * 16, bkof));
#pragma unroll
    for (int kk = 0; kk < 8; kk++) {
        const int cur = kk & 1, nxt = cur ^ 1;
        if (kk < 7) {
            const int ac = abase + (kk + 1) * 16 + akof;
            const int bc = (kk + 1) * 16 + bkof;
#pragma unroll
            for (int mt = 0; mt < 2; mt++) {
                ldsm4(ah[nxt][mt], As + a_sw(arow_base + mt * 16, ac));
                ldsm4(al[nxt][mt], As + a_sw(arow_base + mt * 16, 256 + ac));
            }
#pragma unroll
            for (int np = 0; np < 2; np++)
                ldsm4(br[nxt][np], Bb + b_sw(brow_base + np * 16, bc));
        }
#pragma unroll
        for (int mt = 0; mt < 2; mt++)
#pragma unroll
            for (int nt = 0; nt < 4; nt++)
                mma16816(acc[mt][nt], ah[cur][mt],
                         br[cur][nt >> 1][(nt & 1) * 2], br[cur][nt >> 1][(nt & 1) * 2 + 1]);
#pragma unroll
        for (int mt = 0; mt < 2; mt++)
#pragma unroll
            for (int nt = 0; nt < 4; nt++)
                mma16816(acc[mt][nt], al[cur][mt],
                         br[cur][nt >> 1][(nt & 1) * 2], br[cur][nt >> 1][(nt & 1) * 2 + 1]);
    }
}

// single: B chunk (e_lo) vs a_hi (cols abase..)
__device__ __forceinline__ void pass_single(
    uint32_t As, uint32_t Bb, int abase,
    int arow_base, int akof, int brow_base, int bkof, float acc[2][4][4])
{
    uint32_t ah[2][2][4], br[2][2][4];
#pragma unroll
    for (int mt = 0; mt < 2; mt++)
        ldsm4(ah[0][mt], As + a_sw(arow_base + mt * 16, abase + akof));
#pragma unroll
    for (int np = 0; np < 2; np++)
        ldsm4(br[0][np], Bb + b_sw(brow_base + np * 16, bkof));
#pragma unroll
    for (int kk = 0; kk < 8; kk++) {
        const int cur = kk & 1, nxt = cur ^ 1;
        if (kk < 7) {
            const int ac = abase + (kk + 1) * 16 + akof;
            const int bc = (kk + 1) * 16 + bkof;
#pragma unroll
            for (int mt = 0; mt < 2; mt++)
                ldsm4(ah[nxt][mt], As + a_sw(arow_base + mt * 16, ac));
#pragma unroll
            for (int np = 0; np < 2; np++)
                ldsm4(br[nxt][np], Bb + b_sw(brow_base + np * 16, bc));
        }
#pragma unroll
        for (int mt = 0; mt < 2; mt++)
#pragma unroll
            for (int nt = 0; nt < 4; nt++)
                mma16816(acc[mt][nt], ah[cur][mt],
                         br[cur][nt >> 1][(nt & 1) * 2], br[cur][nt >> 1][(nt & 1) * 2 + 1]);
    }
}

__global__ void __launch_bounds__(512, 1) k_gemm_p() {
    __shared__ unsigned s_run;

    const int tid  = threadIdx.x;
    const int lane = tid & 31;
    const int wid  = tid >> 5;
    const int wm   = wid & 3;
    const int wn   = wid >> 2;
    const int g    = lane >> 2;
    const int cc   = lane & 3;
    const int sub  = lane >> 3;
    const int r8   = lane & 7;

    uint32_t raw  = smem_u32(dsm);
    uint32_t base = (raw + 255u) & ~255u;
    const uint32_t As = base;
    const uint32_t Bbuf0 = base + SM_A_BYTES;

    const int arow_base = wm * 32 + ((sub & 1) << 3) + r8;
    const int akof      = (sub >> 1) << 3;
    const int brow_base = wn * 32 + ((sub >> 1) << 3) + r8;
    const int bkof      = (sub & 1) << 3;

    const float alpha = g_scalars[1];
    const float2* e2 = (const float2*)g_enorm2;

    float bestv[4];
    int   besti[4];
    int   cur_m = -1;

    float acc[2][4][4];
#pragma unroll
    for (int a = 0; a < 2; a++)
#pragma unroll
        for (int b = 0; b < 4; b++)
#pragma unroll
            for (int d = 0; d < 4; d++) acc[a][b][d] = 0.0f;

    while (true) {
        __syncthreads();   // protects s_run reuse + As overwrite vs prior reads
        if (tid == 0) s_run = atomicAdd(&g_unit_ctr, 1u);
        __syncthreads();
        const unsigned run = s_run;
        if (run >= RUNS_TOTAL) break;

        const int m_tile = (int)(run >> 4);
        const int nbase  = (int)(run & 15u) * 1024;

        if (m_tile != cur_m) {
            if (cur_m >= 0) {
#pragma unroll
                for (int mt = 0; mt < 2; mt++)
#pragma unroll
                    for (int h = 0; h < 2; h++) {
                        int mloc = wm * 32 + mt * 16 + h * 8 + g;
                        atomicMin(&g_best[cur_m * 128 + mloc],
                                  pack_key(bestv[mt * 2 + h], (unsigned)besti[mt * 2 + h]));
                    }
            }
#pragma unroll
            for (int i = 0; i < 4; i++) { bestv[i] = 3.4e38f; besti[i] = 0; }
            cur_m = m_tile;
            const int m0 = m_tile * 128;
#pragma unroll
            for (int seg = 0; seg < 2; seg++) {
                const __nv_bfloat16* src = seg ? g_z_lo : g_z_hi;
                for (int f = tid; f < 4096; f += 512) {
                    int row = f >> 5, k = (f & 31) * 8;
                    cp_async16(As + a_sw(row, seg * 256 + k),
                               src + (size_t)(m0 + row) * KDIM + k);
                }
            }
            cp_commit();     // A = one group; covered by first cp_wait below
        }

        // prologue: chunks 0 and 1
        issue_b(g_e_hi, nbase, 0,   Bbuf0 + 0 * SM_B_BYTES, tid);
        issue_b(g_e_hi, nbase, 128, Bbuf0 + 1 * SM_B_BYTES, tid);

#pragma unroll 1
        for (int c = 0; c < 32; c++) {
            if (c < 31) cp_wait<1>(); else cp_wait<0>();
            __syncthreads();
            if (c < 30) {
                const int cn = c + 2;
                const int s  = cn >> 2, p = cn & 3;
                issue_b((p < 2) ? g_e_hi : g_e_lo, nbase + s * 128, (p & 1) * 128,
                        Bbuf0 + (uint32_t)(cn % 3) * SM_B_BYTES, tid);
            }
            const int p = c & 3;
            const int abase = (p & 1) * 128;
            const uint32_t Bb = Bbuf0 + (uint32_t)(c % 3) * SM_B_BYTES;
            if (p < 2)
                pass_dual(As, Bb, abase, arow_base, akof, brow_base, bkof, acc);
            else
                pass_single(As, Bb, abase, arow_base, akof, brow_base, bkof, acc);

            if (p == 3) {
                const int n0 = nbase + (c >> 2) * 128;
#pragma unroll
                for (int mt = 0; mt < 2; mt++) {
#pragma unroll
                    for (int nt = 0; nt < 4; nt++) {
                        const int nloc = wn * 32 + nt * 8 + 2 * cc;
                        const int gn = n0 + nloc;
                        float2 ev = __ldg(e2 + ((unsigned)gn >> 1));
                        float v0 = fmaf(-alpha, acc[mt][nt][0], ev.x);
                        float v1 = fmaf(-alpha, acc[mt][nt][1], ev.y);
                        float v2 = fmaf(-alpha, acc[mt][nt][2], ev.x);
                        float v3 = fmaf(-alpha, acc[mt][nt][3], ev.y);
                        const int i0 = mt * 2, i1 = mt * 2 + 1;
                        if (v0 < bestv[i0]) { bestv[i0] = v0; besti[i0] = gn; }
                        if (v1 < bestv[i0]) { bestv[i0] = v1; besti[i0] = gn + 1; }
                        if (v2 < bestv[i1]) { bestv[i1] = v2; besti[i1] = gn; }
                        if (v3 < bestv[i1]) { bestv[i1] = v3; besti[i1] = gn + 1; }
                        acc[mt][nt][0] = 0.0f; acc[mt][nt][1] = 0.0f;
                        acc[mt][nt][2] = 0.0f; acc[mt][nt][3] = 0.0f;
                    }
                }
            }
        }
    }

    if (cur_m >= 0) {
#pragma unroll
        for (int mt = 0; mt < 2; mt++)
#pragma unroll
            for (int h = 0; h < 2; h++) {
                int mloc = wm * 32 + mt * 16 + h * 8 + g;
                atomicMin(&g_best[cur_m * 128 + mloc],
                          pack_key(bestv[mt * 2 + h], (unsigned)besti[mt * 2 + h]));
            }
    }
}

// ---------------- kernel 5 ----------------
__global__ void k_gather(const float* __restrict__ emb, float* __restrict__ out) {
    float scale = g_scalars[0];
    float lsum = 0.0f;
    for (int e = blockIdx.x * 256 + threadIdx.x; e < M_TOK * KDIM; e += 256 * 256) {
        int t = e >> 8;
        int c = e & 255;
        int idx = (int)(unsigned)(g_best[t] & 0xFFFFFFFFull);
        float zq = emb[(size_t)idx * KDIM + c] * FIXLEN;
        float zt = g_zflat[e] * scale;
        float d = zq - zt;
        lsum += d * d;
        int b  = t >> 10;
        int hw = t & 1023;
        out[(size_t)b * (KDIM * HWSZ) + (size_t)c * HWSZ + hw] = zq;
    }
    __shared__ float sred[256];
    sred[threadIdx.x] = lsum;
    __syncthreads();
    for (int s = 128; s > 0; s >>= 1) {
        if (threadIdx.x < s) sred[threadIdx.x] += sred[threadIdx.x + s];
        __syncthreads();
    }
    if (threadIdx.x == 0) g_diffpart[blockIdx.x] = sred[0];
}

// ---------------- kernel 6 ----------------
__global__ void k_final(float* __restrict__ out, int out_size) {
    __shared__ float s[256];
    s[threadIdx.x] = g_diffpart[threadIdx.x];
    __syncthreads();
    for (int st = 128; st > 0; st >>= 1) {
        if (threadIdx.x < st) s[threadIdx.x] += s[threadIdx.x + st];
        __syncthreads();
    }
    float diff = 0.25f * s[0] / (float)(M_TOK * KDIM);
    if (threadIdx.x == 0 && out_size > NZ) out[NZ] = diff;
    if (out_size >= NZ + 1 + M_TOK) {
        for (int t = threadIdx.x; t < M_TOK; t += 256)
            out[NZ + 1 + t] = (float)(unsigned)(g_best[t] & 0xFFFFFFFFull);
    }
}

// ---------------- launch ----------------
extern "C" void kernel_launch(void* const* d_in, const int* in_sizes, int n_in,
                              void* d_out, int out_size) {
    const float* z   = (const float*)d_in[0];
    const float* emb = (const float*)d_in[1];
    float* out = (float*)d_out;
    (void)in_sizes; (void)n_in;

    const int gemm_smem = 256 + SM_A_BYTES + 3 * SM_B_BYTES;  // 229,632 B
    cudaFuncSetAttribute(k_gemm_p, cudaFuncAttributeMaxDynamicSharedMemorySize, gemm_smem);

    k_prep<<<M_TOK / 256, 256>>>(z);
    k_scale<<<1, 64>>>();
    k_enorm<<<N_EMB / 8, 256>>>(emb);
    k_gemm_p<<<NUM_CTAS, 512, gemm_smem>>>();
    k_gather<<<256, 256>>>(emb, out);
    k_final<<<1, 256>>>(out, out_size);
}